// round 1
// baseline (speedup 1.0000x reference)
#include <cuda_runtime.h>
#include <math.h>

#define B      4096
#define D      512
#define NHALF  2048
#define TM     64
#define TN     64
#define KT     32
#define COLS_PER_BLOCK 512   // 8 col tiles of 64 per block

// ---- scratch (no allocations allowed) ----
__device__ float g_batch[(size_t)B * D];   // 8 MB, fits in L2
__device__ float g_sq[B];
__device__ float g_posdot[B];
__device__ int   g_minneg[B];              // ordered-int encoded min of (sq_j - 2*dot)

__device__ __forceinline__ int f2ord(float f) {
    int i = __float_as_int(f);
    return (i >= 0) ? i : (i ^ 0x7FFFFFFF);
}
__device__ __forceinline__ float ord2f(int i) {
    return __int_as_float((i >= 0) ? i : (i ^ 0x7FFFFFFF));
}

// Kernel 1: gather batch row, row sum-of-squares, positive-pair dot, init mins.
__global__ void prep_kernel(const float* __restrict__ h1, const float* __restrict__ h2) {
    int i = blockIdx.x;
    int p = i ^ NHALF;  // partner index ((i + N) mod 2N)
    const float* __restrict__ row  = (i < NHALF) ? (h1 + (size_t)i * D)
                                                 : (h2 + (size_t)(i - NHALF) * D);
    const float* __restrict__ prow = (p < NHALF) ? (h1 + (size_t)p * D)
                                                 : (h2 + (size_t)(p - NHALF) * D);
    float sq = 0.f, dot = 0.f;
    for (int k = threadIdx.x; k < D; k += blockDim.x) {
        float x = row[k];
        float y = prow[k];
        g_batch[(size_t)i * D + k] = x;
        sq  = fmaf(x, x, sq);
        dot = fmaf(x, y, dot);
    }
    #pragma unroll
    for (int o = 16; o; o >>= 1) {
        sq  += __shfl_xor_sync(0xFFFFFFFFu, sq,  o);
        dot += __shfl_xor_sync(0xFFFFFFFFu, dot, o);
    }
    __shared__ float ssq[4], sdot[4];
    int w = threadIdx.x >> 5;
    if ((threadIdx.x & 31) == 0) { ssq[w] = sq; sdot[w] = dot; }
    __syncthreads();
    if (threadIdx.x == 0) {
        float S = 0.f, T = 0.f;
        #pragma unroll
        for (int j = 0; j < 4; ++j) { S += ssq[j]; T += sdot[j]; }
        g_sq[i]     = S;
        g_posdot[i] = T;
        g_minneg[i] = 0x7FFFFFFF;
    }
}

// Kernel 2: fused fp32 GEMM (G = batch * batch^T) + per-row min of (sq_j - 2*dot),
// excluding j == i and j == partner(i). Distance matrix never materialized.
__global__ __launch_bounds__(256, 2) void gemm_min_kernel() {
    __shared__ float As[KT][TM + 4];
    __shared__ float Bs[KT][TN + 4];
    __shared__ int   smin[TM];

    int tid = threadIdx.x;
    int tx = tid & 15;        // col group
    int ty = tid >> 4;        // row group
    int rowBase  = blockIdx.x * TM;
    int colChunk = blockIdx.y * COLS_PER_BLOCK;

    float rmin[4] = {INFINITY, INFINITY, INFINITY, INFINITY};

    for (int ct = 0; ct < COLS_PER_BLOCK / TN; ++ct) {
        int colBase = colChunk + ct * TN;
        float acc[4][4];
        #pragma unroll
        for (int m = 0; m < 4; ++m)
            #pragma unroll
            for (int n = 0; n < 4; ++n) acc[m][n] = 0.f;

        for (int k0 = 0; k0 < D; k0 += KT) {
            // load A tile (rows) and B tile (cols = rows of same matrix), transposed to [k][r]
            #pragma unroll
            for (int l = 0; l < (TM * KT) / 256; ++l) {
                int e = tid + l * 256;
                int r = e >> 5;       // 0..63
                int k = e & 31;       // 0..31
                As[k][r] = g_batch[(size_t)(rowBase + r) * D + k0 + k];
                Bs[k][r] = g_batch[(size_t)(colBase + r) * D + k0 + k];
            }
            __syncthreads();
            #pragma unroll
            for (int k = 0; k < KT; ++k) {
                float4 a = *(const float4*)&As[k][ty * 4];
                float4 b = *(const float4*)&Bs[k][tx * 4];
                float af[4] = {a.x, a.y, a.z, a.w};
                float bf[4] = {b.x, b.y, b.z, b.w};
                #pragma unroll
                for (int m = 0; m < 4; ++m)
                    #pragma unroll
                    for (int n = 0; n < 4; ++n)
                        acc[m][n] = fmaf(af[m], bf[n], acc[m][n]);
            }
            __syncthreads();
        }

        // fold this tile into the per-row running min of (sq_j - 2*dot)
        #pragma unroll
        for (int n = 0; n < 4; ++n) {
            int j = colBase + tx * 4 + n;
            float sqj = g_sq[j];
            #pragma unroll
            for (int m = 0; m < 4; ++m) {
                int i = rowBase + ty * 4 + m;
                if (j != i && j != (i ^ NHALF)) {
                    float v = fmaf(-2.f, acc[m][n], sqj);
                    rmin[m] = fminf(rmin[m], v);
                }
            }
        }
    }

    // block-level row reduction, then global atomicMin
    if (tid < TM) smin[tid] = 0x7FFFFFFF;
    __syncthreads();
    #pragma unroll
    for (int m = 0; m < 4; ++m)
        atomicMin(&smin[ty * 4 + m], f2ord(rmin[m]));
    __syncthreads();
    if (tid < TM)
        atomicMin(&g_minneg[rowBase + tid], smin[tid]);
}

__device__ __forceinline__ float block_reduce_sum(float v, float* sh, int tid) {
    sh[tid] = v;
    __syncthreads();
    for (int s = 512; s; s >>= 1) {
        if (tid < s) sh[tid] += sh[tid + s];
        __syncthreads();
    }
    float r = sh[0];
    __syncthreads();
    return r;
}

// Kernel 3: clamps, triplet loss, 5 scalar outputs.
__global__ void finalize_kernel(float* __restrict__ out) {
    __shared__ float sh[1024];
    int tid = threadIdx.x;

    float sum_diff = 0.f, sum_rel = 0.f, sum_sq = 0.f;
    float cnt_rel = 0.f, cnt_good = 0.f;

    for (int s = 0; s < B; s += 1024) {
        int i = s + tid;
        float sqi = g_sq[i];
        float d2p = sqi + g_sq[i ^ NHALF] - 2.f * g_posdot[i];
        float hp  = fmaxf(sqrtf(fmaxf(d2p, 1e-14f)), 1e-7f);
        float d2n = sqi + ord2f(g_minneg[i]);
        float hn  = fmaxf(sqrtf(fmaxf(d2n, 1e-14f)), 1e-7f);
        float diff = hp - hn;
        float trip = fmaxf(diff + 0.1f, 0.f);
        sum_diff += diff;
        if (trip > 1e-5f) { sum_rel += trip; cnt_rel += 1.f; }
        if (trip < 1e-5f) cnt_good += 1.f;
        sum_sq += sqi;
    }

    float tot_diff = block_reduce_sum(sum_diff, sh, tid);
    float tot_rel  = block_reduce_sum(sum_rel,  sh, tid);
    float tot_sq   = block_reduce_sum(sum_sq,   sh, tid);
    float tot_crel = block_reduce_sum(cnt_rel,  sh, tid);
    float tot_good = block_reduce_sum(cnt_good, sh, tid);

    if (tid == 0) {
        float nrel = fmaxf(tot_crel, 1.f);
        out[0] = tot_rel / nrel;                 // loss
        out[1] = tot_diff / (float)B;            // mean(differences)
        out[2] = tot_good;                       // good
        out[3] = (float)B - tot_good;            // bad
        out[4] = sqrtf(tot_sq / (float)B);       // sqrt(mean_norm_squared)
    }
}

extern "C" void kernel_launch(void* const* d_in, const int* in_sizes, int n_in,
                              void* d_out, int out_size) {
    const float* h1 = (const float*)d_in[0];
    const float* h2 = (const float*)d_in[1];
    // h3 (d_in[2]) is unused by the reference computation.
    (void)in_sizes; (void)n_in; (void)out_size;

    prep_kernel<<<B, 128>>>(h1, h2);
    dim3 g2(B / TM, B / COLS_PER_BLOCK);   // (64, 8)
    gemm_min_kernel<<<g2, 256>>>();
    finalize_kernel<<<1, 1024>>>((float*)d_out);
}

// round 3
// speedup vs baseline: 5.1837x; 5.1837x over previous
#include <cuda_runtime.h>
#include <cuda_bf16.h>
#include <math.h>
#include <stdint.h>

#define B       4096
#define D       512
#define NHALF   2048
#define BM      128
#define BN      128
#define KC      32
#define NB      (B / BM)        // 32 block-rows
#define NTHREADS 256
#define ROWSTRIDE 80            // 64B data + 16B pad (conflict-free ldmatrix)

// ---- scratch ----
__device__ __nv_bfloat16 g_hi[(size_t)B * D];   // 4 MB
__device__ __nv_bfloat16 g_lo[(size_t)B * D];   // 4 MB
__device__ float g_sq[B];
__device__ float g_posdot[B];
__device__ int   g_minneg[B];

__device__ __forceinline__ int f2ord(float f) {
    int i = __float_as_int(f);
    return (i >= 0) ? i : (i ^ 0x7FFFFFFF);
}
__device__ __forceinline__ float ord2f(int i) {
    return __int_as_float((i >= 0) ? i : (i ^ 0x7FFFFFFF));
}

__device__ __forceinline__ void ldsm_x4(uint32_t& r0, uint32_t& r1, uint32_t& r2, uint32_t& r3,
                                        uint32_t addr) {
    asm volatile("ldmatrix.sync.aligned.m8n8.x4.shared.b16 {%0,%1,%2,%3}, [%4];"
                 : "=r"(r0), "=r"(r1), "=r"(r2), "=r"(r3) : "r"(addr));
}

__device__ __forceinline__ void mma16816(float* c, uint32_t a0, uint32_t a1, uint32_t a2,
                                         uint32_t a3, uint32_t b0, uint32_t b1) {
    asm volatile(
        "mma.sync.aligned.m16n8k16.row.col.f32.bf16.bf16.f32 "
        "{%0,%1,%2,%3}, {%4,%5,%6,%7}, {%8,%9}, {%0,%1,%2,%3};"
        : "+f"(c[0]), "+f"(c[1]), "+f"(c[2]), "+f"(c[3])
        : "r"(a0), "r"(a1), "r"(a2), "r"(a3), "r"(b0), "r"(b1));
}

// ---------------- Kernel 1: prep (unchanged from R1, + hi/lo split) ----------------
__global__ void prep_kernel(const float* __restrict__ h1, const float* __restrict__ h2) {
    int i = blockIdx.x;
    int p = i ^ NHALF;
    const float* __restrict__ row  = (i < NHALF) ? (h1 + (size_t)i * D)
                                                 : (h2 + (size_t)(i - NHALF) * D);
    const float* __restrict__ prow = (p < NHALF) ? (h1 + (size_t)p * D)
                                                 : (h2 + (size_t)(p - NHALF) * D);
    float sq = 0.f, dot = 0.f;
    for (int k = threadIdx.x; k < D; k += blockDim.x) {
        float x = row[k];
        float y = prow[k];
        __nv_bfloat16 hb = __float2bfloat16(x);
        float hf = __bfloat162float(hb);
        g_hi[(size_t)i * D + k] = hb;
        g_lo[(size_t)i * D + k] = __float2bfloat16(x - hf);
        sq  = fmaf(x, x, sq);
        dot = fmaf(x, y, dot);
    }
    #pragma unroll
    for (int o = 16; o; o >>= 1) {
        sq  += __shfl_xor_sync(0xFFFFFFFFu, sq,  o);
        dot += __shfl_xor_sync(0xFFFFFFFFu, dot, o);
    }
    __shared__ float ssq[4], sdot[4];
    int w = threadIdx.x >> 5;
    if ((threadIdx.x & 31) == 0) { ssq[w] = sq; sdot[w] = dot; }
    __syncthreads();
    if (threadIdx.x == 0) {
        float S = 0.f, T = 0.f;
        #pragma unroll
        for (int j = 0; j < 4; ++j) { S += ssq[j]; T += sdot[j]; }
        g_sq[i]     = S;
        g_posdot[i] = T;
        g_minneg[i] = 0x7FFFFFFF;
    }
}

// ---------------- Kernel 2: HMMA split-bf16 Gram + two-sided min (upper triangle) ----------------
__global__ __launch_bounds__(NTHREADS, 2) void gemm_min_kernel() {
    __shared__ char sAhi[BM * ROWSTRIDE];
    __shared__ char sAlo[BM * ROWSTRIDE];
    __shared__ char sBhi[BN * ROWSTRIDE];
    __shared__ char sBlo[BN * ROWSTRIDE];
    __shared__ float s_sqrow[BM];
    __shared__ float s_sqcol[BN];
    __shared__ int   s_rowmin[BM];
    __shared__ int   s_colmin[BN];

    const int tid  = threadIdx.x;
    const int wid  = tid >> 5;
    const int lane = tid & 31;
    const int warpRow = wid >> 2;     // 0..1  (64-row slab)
    const int warpCol = wid & 3;      // 0..3  (32-col slab)

    // triangular block decode: blockIdx.x -> (bi, bj), bi <= bj
    int t = blockIdx.x, bi = 0;
    while (t >= NB - bi) { t -= NB - bi; ++bi; }
    const int bj = bi + t;
    const int rowBase = bi * BM;
    const int colBase = bj * BN;
    const bool diag = (bi == bj);

    const uint32_t aHiB = (uint32_t)__cvta_generic_to_shared(sAhi);
    const uint32_t aLoB = (uint32_t)__cvta_generic_to_shared(sAlo);
    const uint32_t bHiB = (uint32_t)__cvta_generic_to_shared(sBhi);
    const uint32_t bLoB = (uint32_t)__cvta_generic_to_shared(sBlo);

    if (tid < BM) {
        s_sqrow[tid]  = g_sq[rowBase + tid];
        s_sqcol[tid]  = g_sq[colBase + tid];
        s_rowmin[tid] = 0x7FFFFFFF;
        s_colmin[tid] = 0x7FFFFFFF;
    }

    float acc[4][4][4];
    #pragma unroll
    for (int m = 0; m < 4; ++m)
        #pragma unroll
        for (int n = 0; n < 4; ++n)
            #pragma unroll
            for (int c = 0; c < 4; ++c) acc[m][n][c] = 0.f;

    for (int kc = 0; kc < D / KC; ++kc) {
        const int kel = kc * KC;
        // stage A tiles (hi+lo)
        #pragma unroll
        for (int l = 0; l < (BM * 4) / NTHREADS; ++l) {
            int s = tid + l * NTHREADS;
            int r = s >> 2, c = s & 3;
            uint32_t off = (uint32_t)(r * ROWSTRIDE + c * 16);
            size_t src = (size_t)(rowBase + r) * D + kel + (size_t)c * 8;
            *(uint4*)(sAhi + off) = *(const uint4*)&g_hi[src];
            *(uint4*)(sAlo + off) = *(const uint4*)&g_lo[src];
        }
        // stage B tiles (hi+lo)
        #pragma unroll
        for (int l = 0; l < (BN * 4) / NTHREADS; ++l) {
            int s = tid + l * NTHREADS;
            int r = s >> 2, c = s & 3;
            uint32_t off = (uint32_t)(r * ROWSTRIDE + c * 16);
            size_t src = (size_t)(colBase + r) * D + kel + (size_t)c * 8;
            *(uint4*)(sBhi + off) = *(const uint4*)&g_hi[src];
            *(uint4*)(sBlo + off) = *(const uint4*)&g_lo[src];
        }
        __syncthreads();

        #pragma unroll
        for (int kk = 0; kk < 2; ++kk) {
            const uint32_t kb = (uint32_t)(kk * 32 + (lane >> 4) * 16);
            // A fragments
            uint32_t ah[4][4], al[4][4];
            #pragma unroll
            for (int m = 0; m < 4; ++m) {
                uint32_t roff = (uint32_t)((warpRow * 64 + m * 16 + (lane & 15)) * ROWSTRIDE) + kb;
                ldsm_x4(ah[m][0], ah[m][1], ah[m][2], ah[m][3], aHiB + roff);
                ldsm_x4(al[m][0], al[m][1], al[m][2], al[m][3], aLoB + roff);
            }
            // B fragments (x4 covers n16: regs {q0,q2} -> n-frag even, {q1,q3} -> odd)
            uint32_t bh[4][2], bl[4][2];
            #pragma unroll
            for (int nb = 0; nb < 2; ++nb) {
                uint32_t roff = (uint32_t)((warpCol * 32 + nb * 16 + (lane & 15)) * ROWSTRIDE) + kb;
                uint32_t q0, q1, q2, q3;
                ldsm_x4(q0, q1, q2, q3, bHiB + roff);
                bh[nb * 2 + 0][0] = q0; bh[nb * 2 + 0][1] = q2;
                bh[nb * 2 + 1][0] = q1; bh[nb * 2 + 1][1] = q3;
                ldsm_x4(q0, q1, q2, q3, bLoB + roff);
                bl[nb * 2 + 0][0] = q0; bl[nb * 2 + 0][1] = q2;
                bl[nb * 2 + 1][0] = q1; bl[nb * 2 + 1][1] = q3;
            }
            #pragma unroll
            for (int m = 0; m < 4; ++m)
                #pragma unroll
                for (int n = 0; n < 4; ++n) {
                    mma16816(acc[m][n], ah[m][0], ah[m][1], ah[m][2], ah[m][3], bh[n][0], bh[n][1]);
                    mma16816(acc[m][n], ah[m][0], ah[m][1], ah[m][2], ah[m][3], bl[n][0], bl[n][1]);
                    mma16816(acc[m][n], al[m][0], al[m][1], al[m][2], al[m][3], bh[n][0], bh[n][1]);
                }
        }
        __syncthreads();
    }

    // ---- epilogue: two-sided masked min ----
    float rmin[4][2], cmin[4][2];
    #pragma unroll
    for (int a = 0; a < 4; ++a)
        #pragma unroll
        for (int b2 = 0; b2 < 2; ++b2) { rmin[a][b2] = INFINITY; cmin[a][b2] = INFINITY; }

    #pragma unroll
    for (int m = 0; m < 4; ++m) {
        #pragma unroll
        for (int h = 0; h < 2; ++h) {
            int rl = warpRow * 64 + m * 16 + h * 8 + (lane >> 2);
            int i  = rowBase + rl;
            float sqi = s_sqrow[rl];
            #pragma unroll
            for (int n = 0; n < 4; ++n) {
                #pragma unroll
                for (int e = 0; e < 2; ++e) {
                    int cl = warpCol * 32 + n * 8 + (lane & 3) * 2 + e;
                    int j  = colBase + cl;
                    float a = acc[m][n][h * 2 + e];
                    if (j != i && j != (i ^ NHALF)) {
                        rmin[m][h] = fminf(rmin[m][h], fmaf(-2.f, a, s_sqcol[cl]));
                        cmin[n][e] = fminf(cmin[n][e], fmaf(-2.f, a, sqi));
                    }
                }
            }
        }
    }

    // row mins: reduce across lane&3 (threads sharing a row)
    #pragma unroll
    for (int m = 0; m < 4; ++m)
        #pragma unroll
        for (int h = 0; h < 2; ++h) {
            float v = rmin[m][h];
            v = fminf(v, __shfl_xor_sync(0xFFFFFFFFu, v, 1));
            v = fminf(v, __shfl_xor_sync(0xFFFFFFFFu, v, 2));
            if ((lane & 3) == 0)
                atomicMin(&s_rowmin[warpRow * 64 + m * 16 + h * 8 + (lane >> 2)], f2ord(v));
        }
    // col mins: reduce across lane>>2 (threads sharing a column)
    if (!diag) {
        #pragma unroll
        for (int n = 0; n < 4; ++n)
            #pragma unroll
            for (int e = 0; e < 2; ++e) {
                float v = cmin[n][e];
                v = fminf(v, __shfl_xor_sync(0xFFFFFFFFu, v, 4));
                v = fminf(v, __shfl_xor_sync(0xFFFFFFFFu, v, 8));
                v = fminf(v, __shfl_xor_sync(0xFFFFFFFFu, v, 16));
                if ((lane >> 2) == 0)
                    atomicMin(&s_colmin[warpCol * 32 + n * 8 + (lane & 3) * 2 + e], f2ord(v));
            }
    }
    __syncthreads();

    if (tid < BM)
        atomicMin(&g_minneg[rowBase + tid], s_rowmin[tid]);
    else if (!diag)
        atomicMin(&g_minneg[colBase + (tid - BM)], s_colmin[tid - BM]);
}

// ---------------- Kernel 3: finalize ----------------
__device__ __forceinline__ float block_reduce_sum(float v, float* sh, int tid) {
    sh[tid] = v;
    __syncthreads();
    for (int s = 512; s; s >>= 1) {
        if (tid < s) sh[tid] += sh[tid + s];
        __syncthreads();
    }
    float r = sh[0];
    __syncthreads();
    return r;
}

__global__ void finalize_kernel(float* __restrict__ out) {
    __shared__ float sh[1024];
    int tid = threadIdx.x;

    float sum_diff = 0.f, sum_rel = 0.f, sum_sq = 0.f;
    float cnt_rel = 0.f, cnt_good = 0.f;

    for (int s = 0; s < B; s += 1024) {
        int i = s + tid;
        float sqi = g_sq[i];
        float d2p = sqi + g_sq[i ^ NHALF] - 2.f * g_posdot[i];
        float hp  = fmaxf(sqrtf(fmaxf(d2p, 1e-14f)), 1e-7f);
        float d2n = sqi + ord2f(g_minneg[i]);
        float hn  = fmaxf(sqrtf(fmaxf(d2n, 1e-14f)), 1e-7f);
        float diff = hp - hn;
        float trip = fmaxf(diff + 0.1f, 0.f);
        sum_diff += diff;
        if (trip > 1e-5f) { sum_rel += trip; cnt_rel += 1.f; }
        if (trip < 1e-5f) cnt_good += 1.f;
        sum_sq += sqi;
    }

    float tot_diff = block_reduce_sum(sum_diff, sh, tid);
    float tot_rel  = block_reduce_sum(sum_rel,  sh, tid);
    float tot_sq   = block_reduce_sum(sum_sq,   sh, tid);
    float tot_crel = block_reduce_sum(cnt_rel,  sh, tid);
    float tot_good = block_reduce_sum(cnt_good, sh, tid);

    if (tid == 0) {
        float nrel = fmaxf(tot_crel, 1.f);
        out[0] = tot_rel / nrel;
        out[1] = tot_diff / (float)B;
        out[2] = tot_good;
        out[3] = (float)B - tot_good;
        out[4] = sqrtf(tot_sq / (float)B);
    }
}

extern "C" void kernel_launch(void* const* d_in, const int* in_sizes, int n_in,
                              void* d_out, int out_size) {
    const float* h1 = (const float*)d_in[0];
    const float* h2 = (const float*)d_in[1];
    (void)in_sizes; (void)n_in; (void)out_size;

    prep_kernel<<<B, 128>>>(h1, h2);
    gemm_min_kernel<<<NB * (NB + 1) / 2, NTHREADS>>>();   // 528 CTAs (upper triangle)
    finalize_kernel<<<1, 1024>>>((float*)d_out);
}

// round 4
// speedup vs baseline: 5.4703x; 1.0553x over previous
#include <cuda_runtime.h>
#include <cuda_bf16.h>
#include <math.h>
#include <stdint.h>

#define B       4096
#define D       512
#define NHALF   2048
#define BM      128
#define BN      128
#define KC      32
#define NC      (D / KC)        // 16 chunks
#define NB      (B / BM)        // 32 block-rows
#define NTHREADS 256
#define ROWSTRIDE 80            // 64B data + 16B pad (16B-aligned, conflict-free ldmatrix)

#define TILE_BYTES   (BM * ROWSTRIDE)        // 10240
#define STAGE_BYTES  (4 * TILE_BYTES)        // 40960 (Ahi,Alo,Bhi,Blo)
#define SM_SQROW     (2 * STAGE_BYTES)       // 81920
#define SM_SQCOL     (SM_SQROW + BM * 4)
#define SM_ROWMIN    (SM_SQCOL + BN * 4)
#define SM_COLMIN    (SM_ROWMIN + BM * 4)
#define SM_TOTAL     (SM_COLMIN + BN * 4)    // 83968

// ---- scratch ----
__device__ __nv_bfloat16 g_hi[(size_t)B * D];   // 4 MB
__device__ __nv_bfloat16 g_lo[(size_t)B * D];   // 4 MB
__device__ float g_sq[B];
__device__ float g_posdot[B];
__device__ int   g_minneg[B];

__device__ __forceinline__ int f2ord(float f) {
    int i = __float_as_int(f);
    return (i >= 0) ? i : (i ^ 0x7FFFFFFF);
}
__device__ __forceinline__ float ord2f(int i) {
    return __int_as_float((i >= 0) ? i : (i ^ 0x7FFFFFFF));
}

__device__ __forceinline__ void ldsm_x4(uint32_t& r0, uint32_t& r1, uint32_t& r2, uint32_t& r3,
                                        uint32_t addr) {
    asm volatile("ldmatrix.sync.aligned.m8n8.x4.shared.b16 {%0,%1,%2,%3}, [%4];"
                 : "=r"(r0), "=r"(r1), "=r"(r2), "=r"(r3) : "r"(addr));
}

__device__ __forceinline__ void mma16816(float* c, uint32_t a0, uint32_t a1, uint32_t a2,
                                         uint32_t a3, uint32_t b0, uint32_t b1) {
    asm volatile(
        "mma.sync.aligned.m16n8k16.row.col.f32.bf16.bf16.f32 "
        "{%0,%1,%2,%3}, {%4,%5,%6,%7}, {%8,%9}, {%0,%1,%2,%3};"
        : "+f"(c[0]), "+f"(c[1]), "+f"(c[2]), "+f"(c[3])
        : "r"(a0), "r"(a1), "r"(a2), "r"(a3), "r"(b0), "r"(b1));
}

__device__ __forceinline__ void cp_async16(uint32_t dst, const void* src) {
    asm volatile("cp.async.cg.shared.global [%0], [%1], 16;" :: "r"(dst), "l"(src));
}
#define CP_COMMIT()  asm volatile("cp.async.commit_group;" ::: "memory")
#define CP_WAIT(n)   asm volatile("cp.async.wait_group %0;" :: "n"(n) : "memory")

// ---------------- Kernel 1: prep ----------------
__global__ void prep_kernel(const float* __restrict__ h1, const float* __restrict__ h2) {
    int i = blockIdx.x;
    int p = i ^ NHALF;
    const float* __restrict__ row  = (i < NHALF) ? (h1 + (size_t)i * D)
                                                 : (h2 + (size_t)(i - NHALF) * D);
    const float* __restrict__ prow = (p < NHALF) ? (h1 + (size_t)p * D)
                                                 : (h2 + (size_t)(p - NHALF) * D);
    float sq = 0.f, dot = 0.f;
    for (int k = threadIdx.x; k < D; k += blockDim.x) {
        float x = row[k];
        float y = prow[k];
        __nv_bfloat16 hb = __float2bfloat16(x);
        float hf = __bfloat162float(hb);
        g_hi[(size_t)i * D + k] = hb;
        g_lo[(size_t)i * D + k] = __float2bfloat16(x - hf);
        sq  = fmaf(x, x, sq);
        dot = fmaf(x, y, dot);
    }
    #pragma unroll
    for (int o = 16; o; o >>= 1) {
        sq  += __shfl_xor_sync(0xFFFFFFFFu, sq,  o);
        dot += __shfl_xor_sync(0xFFFFFFFFu, dot, o);
    }
    __shared__ float ssq[4], sdot[4];
    int w = threadIdx.x >> 5;
    if ((threadIdx.x & 31) == 0) { ssq[w] = sq; sdot[w] = dot; }
    __syncthreads();
    if (threadIdx.x == 0) {
        float S = 0.f, T = 0.f;
        #pragma unroll
        for (int j = 0; j < 4; ++j) { S += ssq[j]; T += sdot[j]; }
        g_sq[i]     = S;
        g_posdot[i] = T;
        g_minneg[i] = 0x7FFFFFFF;
    }
}

// ---------------- Kernel 2: pipelined HMMA split-bf16 Gram + two-sided min ----------------
__global__ __launch_bounds__(NTHREADS, 2) void gemm_min_kernel() {
    extern __shared__ char smem[];
    const uint32_t sb = (uint32_t)__cvta_generic_to_shared(smem);

    const int tid  = threadIdx.x;
    const int wid  = tid >> 5;
    const int lane = tid & 31;
    const int warpRow = wid >> 2;     // 0..1
    const int warpCol = wid & 3;      // 0..3

    // triangular block decode
    int t = blockIdx.x, bi = 0;
    while (t >= NB - bi) { t -= NB - bi; ++bi; }
    const int bj = bi + t;
    const int rowBase = bi * BM;
    const int colBase = bj * BN;
    const bool diag = (bi == bj);

    float* s_sqrow = (float*)(smem + SM_SQROW);
    float* s_sqcol = (float*)(smem + SM_SQCOL);
    int*   s_rowmin = (int*)(smem + SM_ROWMIN);
    int*   s_colmin = (int*)(smem + SM_COLMIN);

    if (tid < BM) {
        s_sqrow[tid]  = g_sq[rowBase + tid];
        s_sqcol[tid]  = g_sq[colBase + tid];
        s_rowmin[tid] = 0x7FFFFFFF;
        s_colmin[tid] = 0x7FFFFFFF;
    }

    // per-thread staging indices: 2 A-rows, 2 B-rows (16B each)
    const int lr0 = (tid + 0 * NTHREADS) >> 2, lc0 = (tid + 0 * NTHREADS) & 3;
    const int lr1 = (tid + 1 * NTHREADS) >> 2, lc1 = (tid + 1 * NTHREADS) & 3;

    auto stage_load = [&](int s, int kc) {
        const int kel = kc * KC;
        const uint32_t st = sb + (uint32_t)s * STAGE_BYTES;
        uint32_t o0 = (uint32_t)(lr0 * ROWSTRIDE + lc0 * 16);
        uint32_t o1 = (uint32_t)(lr1 * ROWSTRIDE + lc1 * 16);
        size_t a0 = (size_t)(rowBase + lr0) * D + kel + (size_t)lc0 * 8;
        size_t a1 = (size_t)(rowBase + lr1) * D + kel + (size_t)lc1 * 8;
        size_t b0 = (size_t)(colBase + lr0) * D + kel + (size_t)lc0 * 8;
        size_t b1 = (size_t)(colBase + lr1) * D + kel + (size_t)lc1 * 8;
        cp_async16(st + 0 * TILE_BYTES + o0, &g_hi[a0]);
        cp_async16(st + 0 * TILE_BYTES + o1, &g_hi[a1]);
        cp_async16(st + 1 * TILE_BYTES + o0, &g_lo[a0]);
        cp_async16(st + 1 * TILE_BYTES + o1, &g_lo[a1]);
        cp_async16(st + 2 * TILE_BYTES + o0, &g_hi[b0]);
        cp_async16(st + 2 * TILE_BYTES + o1, &g_hi[b1]);
        cp_async16(st + 3 * TILE_BYTES + o0, &g_lo[b0]);
        cp_async16(st + 3 * TILE_BYTES + o1, &g_lo[b1]);
    };

    float acc[4][4][4];
    #pragma unroll
    for (int m = 0; m < 4; ++m)
        #pragma unroll
        for (int n = 0; n < 4; ++n)
            #pragma unroll
            for (int c = 0; c < 4; ++c) acc[m][n][c] = 0.f;

    stage_load(0, 0);
    CP_COMMIT();

    for (int kc = 0; kc < NC; ++kc) {
        if (kc + 1 < NC) {
            stage_load((kc + 1) & 1, kc + 1);
            CP_COMMIT();
            CP_WAIT(1);
        } else {
            CP_WAIT(0);
        }
        __syncthreads();

        const uint32_t st = sb + (uint32_t)(kc & 1) * STAGE_BYTES;
        const uint32_t aHiB = st;
        const uint32_t aLoB = st + 1 * TILE_BYTES;
        const uint32_t bHiB = st + 2 * TILE_BYTES;
        const uint32_t bLoB = st + 3 * TILE_BYTES;

        #pragma unroll
        for (int kk = 0; kk < 2; ++kk) {
            const uint32_t kb = (uint32_t)(kk * 32 + (lane >> 4) * 16);
            uint32_t ah[4][4], al[4][4];
            #pragma unroll
            for (int m = 0; m < 4; ++m) {
                uint32_t roff = (uint32_t)((warpRow * 64 + m * 16 + (lane & 15)) * ROWSTRIDE) + kb;
                ldsm_x4(ah[m][0], ah[m][1], ah[m][2], ah[m][3], aHiB + roff);
                ldsm_x4(al[m][0], al[m][1], al[m][2], al[m][3], aLoB + roff);
            }
            uint32_t bh[4][2], bl[4][2];
            #pragma unroll
            for (int nb = 0; nb < 2; ++nb) {
                uint32_t roff = (uint32_t)((warpCol * 32 + nb * 16 + (lane & 15)) * ROWSTRIDE) + kb;
                uint32_t q0, q1, q2, q3;
                ldsm_x4(q0, q1, q2, q3, bHiB + roff);
                bh[nb * 2 + 0][0] = q0; bh[nb * 2 + 0][1] = q2;
                bh[nb * 2 + 1][0] = q1; bh[nb * 2 + 1][1] = q3;
                ldsm_x4(q0, q1, q2, q3, bLoB + roff);
                bl[nb * 2 + 0][0] = q0; bl[nb * 2 + 0][1] = q2;
                bl[nb * 2 + 1][0] = q1; bl[nb * 2 + 1][1] = q3;
            }
            #pragma unroll
            for (int m = 0; m < 4; ++m)
                #pragma unroll
                for (int n = 0; n < 4; ++n) {
                    mma16816(acc[m][n], ah[m][0], ah[m][1], ah[m][2], ah[m][3], bh[n][0], bh[n][1]);
                    mma16816(acc[m][n], ah[m][0], ah[m][1], ah[m][2], ah[m][3], bl[n][0], bl[n][1]);
                    mma16816(acc[m][n], al[m][0], al[m][1], al[m][2], al[m][3], bh[n][0], bh[n][1]);
                }
        }
        __syncthreads();
    }

    // ---- epilogue: two-sided masked min ----
    float rmin[4][2], cmin[4][2];
    #pragma unroll
    for (int a = 0; a < 4; ++a)
        #pragma unroll
        for (int b2 = 0; b2 < 2; ++b2) { rmin[a][b2] = INFINITY; cmin[a][b2] = INFINITY; }

    #pragma unroll
    for (int m = 0; m < 4; ++m) {
        #pragma unroll
        for (int h = 0; h < 2; ++h) {
            int rl = warpRow * 64 + m * 16 + h * 8 + (lane >> 2);
            int i  = rowBase + rl;
            float sqi = s_sqrow[rl];
            #pragma unroll
            for (int n = 0; n < 4; ++n) {
                #pragma unroll
                for (int e = 0; e < 2; ++e) {
                    int cl = warpCol * 32 + n * 8 + (lane & 3) * 2 + e;
                    int j  = colBase + cl;
                    float a = acc[m][n][h * 2 + e];
                    if (j != i && j != (i ^ NHALF)) {
                        rmin[m][h] = fminf(rmin[m][h], fmaf(-2.f, a, s_sqcol[cl]));
                        cmin[n][e] = fminf(cmin[n][e], fmaf(-2.f, a, sqi));
                    }
                }
            }
        }
    }

    #pragma unroll
    for (int m = 0; m < 4; ++m)
        #pragma unroll
        for (int h = 0; h < 2; ++h) {
            float v = rmin[m][h];
            v = fminf(v, __shfl_xor_sync(0xFFFFFFFFu, v, 1));
            v = fminf(v, __shfl_xor_sync(0xFFFFFFFFu, v, 2));
            if ((lane & 3) == 0)
                atomicMin(&s_rowmin[warpRow * 64 + m * 16 + h * 8 + (lane >> 2)], f2ord(v));
        }
    if (!diag) {
        #pragma unroll
        for (int n = 0; n < 4; ++n)
            #pragma unroll
            for (int e = 0; e < 2; ++e) {
                float v = cmin[n][e];
                v = fminf(v, __shfl_xor_sync(0xFFFFFFFFu, v, 4));
                v = fminf(v, __shfl_xor_sync(0xFFFFFFFFu, v, 8));
                v = fminf(v, __shfl_xor_sync(0xFFFFFFFFu, v, 16));
                if ((lane >> 2) == 0)
                    atomicMin(&s_colmin[warpCol * 32 + n * 8 + (lane & 3) * 2 + e], f2ord(v));
            }
    }
    __syncthreads();

    if (tid < BM)
        atomicMin(&g_minneg[rowBase + tid], s_rowmin[tid]);
    else if (!diag)
        atomicMin(&g_minneg[colBase + (tid - BM)], s_colmin[tid - BM]);
}

// ---------------- Kernel 3: finalize ----------------
__device__ __forceinline__ float block_reduce_sum(float v, float* sh, int tid) {
    sh[tid] = v;
    __syncthreads();
    for (int s = 512; s; s >>= 1) {
        if (tid < s) sh[tid] += sh[tid + s];
        __syncthreads();
    }
    float r = sh[0];
    __syncthreads();
    return r;
}

__global__ void finalize_kernel(float* __restrict__ out) {
    __shared__ float sh[1024];
    int tid = threadIdx.x;

    float sum_diff = 0.f, sum_rel = 0.f, sum_sq = 0.f;
    float cnt_rel = 0.f, cnt_good = 0.f;

    for (int s = 0; s < B; s += 1024) {
        int i = s + tid;
        float sqi = g_sq[i];
        float d2p = sqi + g_sq[i ^ NHALF] - 2.f * g_posdot[i];
        float hp  = fmaxf(sqrtf(fmaxf(d2p, 1e-14f)), 1e-7f);
        float d2n = sqi + ord2f(g_minneg[i]);
        float hn  = fmaxf(sqrtf(fmaxf(d2n, 1e-14f)), 1e-7f);
        float diff = hp - hn;
        float trip = fmaxf(diff + 0.1f, 0.f);
        sum_diff += diff;
        if (trip > 1e-5f) { sum_rel += trip; cnt_rel += 1.f; }
        if (trip < 1e-5f) cnt_good += 1.f;
        sum_sq += sqi;
    }

    float tot_diff = block_reduce_sum(sum_diff, sh, tid);
    float tot_rel  = block_reduce_sum(sum_rel,  sh, tid);
    float tot_sq   = block_reduce_sum(sum_sq,   sh, tid);
    float tot_crel = block_reduce_sum(cnt_rel,  sh, tid);
    float tot_good = block_reduce_sum(cnt_good, sh, tid);

    if (tid == 0) {
        float nrel = fmaxf(tot_crel, 1.f);
        out[0] = tot_rel / nrel;
        out[1] = tot_diff / (float)B;
        out[2] = tot_good;
        out[3] = (float)B - tot_good;
        out[4] = sqrtf(tot_sq / (float)B);
    }
}

extern "C" void kernel_launch(void* const* d_in, const int* in_sizes, int n_in,
                              void* d_out, int out_size) {
    const float* h1 = (const float*)d_in[0];
    const float* h2 = (const float*)d_in[1];
    (void)in_sizes; (void)n_in; (void)out_size;

    static int smem_set = 0;
    if (!smem_set) {
        cudaFuncSetAttribute(gemm_min_kernel,
                             cudaFuncAttributeMaxDynamicSharedMemorySize, SM_TOTAL);
        smem_set = 1;
    }

    prep_kernel<<<B, 128>>>(h1, h2);
    gemm_min_kernel<<<NB * (NB + 1) / 2, NTHREADS, SM_TOTAL>>>();
    finalize_kernel<<<1, 1024>>>((float*)d_out);
}

// round 5
// speedup vs baseline: 10.8469x; 1.9829x over previous
#include <cuda_runtime.h>
#include <cuda_fp16.h>
#include <math.h>
#include <stdint.h>

#define B       4096
#define D       512
#define NHALF   2048
#define BM      128
#define BN      128
#define KC      32
#define NC      (D / KC)        // 16 chunks
#define NB      (B / BM)        // 32 block-rows
#define NTHREADS 256
#define ROWSTRIDE 80            // 64B data + 16B pad (16B-aligned, conflict-free ldmatrix)

#define TILE_BYTES   (BM * ROWSTRIDE)        // 10240
#define STAGE_BYTES  (2 * TILE_BYTES)        // 20480 (A, B)
#define SM_SQROW     (2 * STAGE_BYTES)       // 40960
#define SM_SQCOL     (SM_SQROW + BM * 4)
#define SM_ROWMIN    (SM_SQCOL + BN * 4)
#define SM_COLMIN    (SM_ROWMIN + BM * 4)
#define SM_TOTAL     (SM_COLMIN + BN * 4)    // 43008

// ---- scratch ----
__device__ __half g_h[(size_t)B * D];   // 4 MB (fp16 of batch)
__device__ float g_sq[B];
__device__ float g_posdot[B];
__device__ int   g_minneg[B];

__device__ __forceinline__ int f2ord(float f) {
    int i = __float_as_int(f);
    return (i >= 0) ? i : (i ^ 0x7FFFFFFF);
}
__device__ __forceinline__ float ord2f(int i) {
    return __int_as_float((i >= 0) ? i : (i ^ 0x7FFFFFFF));
}

__device__ __forceinline__ void ldsm_x4(uint32_t& r0, uint32_t& r1, uint32_t& r2, uint32_t& r3,
                                        uint32_t addr) {
    asm volatile("ldmatrix.sync.aligned.m8n8.x4.shared.b16 {%0,%1,%2,%3}, [%4];"
                 : "=r"(r0), "=r"(r1), "=r"(r2), "=r"(r3) : "r"(addr));
}

__device__ __forceinline__ void mma16816(float* c, uint32_t a0, uint32_t a1, uint32_t a2,
                                         uint32_t a3, uint32_t b0, uint32_t b1) {
    asm volatile(
        "mma.sync.aligned.m16n8k16.row.col.f32.f16.f16.f32 "
        "{%0,%1,%2,%3}, {%4,%5,%6,%7}, {%8,%9}, {%0,%1,%2,%3};"
        : "+f"(c[0]), "+f"(c[1]), "+f"(c[2]), "+f"(c[3])
        : "r"(a0), "r"(a1), "r"(a2), "r"(a3), "r"(b0), "r"(b1));
}

__device__ __forceinline__ void cp_async16(uint32_t dst, const void* src) {
    asm volatile("cp.async.cg.shared.global [%0], [%1], 16;" :: "r"(dst), "l"(src));
}
#define CP_COMMIT()  asm volatile("cp.async.commit_group;" ::: "memory")
#define CP_WAIT(n)   asm volatile("cp.async.wait_group %0;" :: "n"(n) : "memory")

// ---------------- Kernel 1: prep ----------------
__global__ void prep_kernel(const float* __restrict__ h1, const float* __restrict__ h2) {
    int i = blockIdx.x;
    int p = i ^ NHALF;
    const float* __restrict__ row  = (i < NHALF) ? (h1 + (size_t)i * D)
                                                 : (h2 + (size_t)(i - NHALF) * D);
    const float* __restrict__ prow = (p < NHALF) ? (h1 + (size_t)p * D)
                                                 : (h2 + (size_t)(p - NHALF) * D);
    float sq = 0.f, dot = 0.f;
    for (int k = threadIdx.x; k < D; k += blockDim.x) {
        float x = row[k];
        float y = prow[k];
        g_h[(size_t)i * D + k] = __float2half(x);
        sq  = fmaf(x, x, sq);
        dot = fmaf(x, y, dot);
    }
    #pragma unroll
    for (int o = 16; o; o >>= 1) {
        sq  += __shfl_xor_sync(0xFFFFFFFFu, sq,  o);
        dot += __shfl_xor_sync(0xFFFFFFFFu, dot, o);
    }
    __shared__ float ssq[4], sdot[4];
    int w = threadIdx.x >> 5;
    if ((threadIdx.x & 31) == 0) { ssq[w] = sq; sdot[w] = dot; }
    __syncthreads();
    if (threadIdx.x == 0) {
        float S = 0.f, T = 0.f;
        #pragma unroll
        for (int j = 0; j < 4; ++j) { S += ssq[j]; T += sdot[j]; }
        g_sq[i]     = S;
        g_posdot[i] = T;
        g_minneg[i] = 0x7FFFFFFF;
    }
}

// ---------------- Kernel 2: pipelined fp16 HMMA Gram + two-sided min ----------------
__global__ __launch_bounds__(NTHREADS, 2) void gemm_min_kernel() {
    extern __shared__ char smem[];
    const uint32_t sb = (uint32_t)__cvta_generic_to_shared(smem);

    const int tid  = threadIdx.x;
    const int wid  = tid >> 5;
    const int lane = tid & 31;
    const int warpRow = wid >> 2;     // 0..1
    const int warpCol = wid & 3;      // 0..3

    // triangular block decode
    int t = blockIdx.x, bi = 0;
    while (t >= NB - bi) { t -= NB - bi; ++bi; }
    const int bj = bi + t;
    const int rowBase = bi * BM;
    const int colBase = bj * BN;
    const bool diag = (bi == bj);

    float* s_sqrow = (float*)(smem + SM_SQROW);
    float* s_sqcol = (float*)(smem + SM_SQCOL);
    int*   s_rowmin = (int*)(smem + SM_ROWMIN);
    int*   s_colmin = (int*)(smem + SM_COLMIN);

    if (tid < BM) {
        s_sqrow[tid]  = g_sq[rowBase + tid];
        s_sqcol[tid]  = g_sq[colBase + tid];
        s_rowmin[tid] = 0x7FFFFFFF;
        s_colmin[tid] = 0x7FFFFFFF;
    }

    // per-thread staging: 2 A-rows, 2 B-rows (16B each)
    const int lr0 = (tid + 0 * NTHREADS) >> 2, lc0 = (tid + 0 * NTHREADS) & 3;
    const int lr1 = (tid + 1 * NTHREADS) >> 2, lc1 = (tid + 1 * NTHREADS) & 3;

    auto stage_load = [&](int s, int kc) {
        const int kel = kc * KC;
        const uint32_t st = sb + (uint32_t)s * STAGE_BYTES;
        uint32_t o0 = (uint32_t)(lr0 * ROWSTRIDE + lc0 * 16);
        uint32_t o1 = (uint32_t)(lr1 * ROWSTRIDE + lc1 * 16);
        cp_async16(st + o0,              &g_h[(size_t)(rowBase + lr0) * D + kel + (size_t)lc0 * 8]);
        cp_async16(st + o1,              &g_h[(size_t)(rowBase + lr1) * D + kel + (size_t)lc1 * 8]);
        cp_async16(st + TILE_BYTES + o0, &g_h[(size_t)(colBase + lr0) * D + kel + (size_t)lc0 * 8]);
        cp_async16(st + TILE_BYTES + o1, &g_h[(size_t)(colBase + lr1) * D + kel + (size_t)lc1 * 8]);
    };

    float acc[4][4][4];
    #pragma unroll
    for (int m = 0; m < 4; ++m)
        #pragma unroll
        for (int n = 0; n < 4; ++n)
            #pragma unroll
            for (int c = 0; c < 4; ++c) acc[m][n][c] = 0.f;

    stage_load(0, 0);
    CP_COMMIT();

    for (int kc = 0; kc < NC; ++kc) {
        if (kc + 1 < NC) {
            stage_load((kc + 1) & 1, kc + 1);
            CP_COMMIT();
            CP_WAIT(1);
        } else {
            CP_WAIT(0);
        }
        __syncthreads();

        const uint32_t aB = sb + (uint32_t)(kc & 1) * STAGE_BYTES;
        const uint32_t bB = aB + TILE_BYTES;

        #pragma unroll
        for (int kk = 0; kk < 2; ++kk) {
            const uint32_t kb = (uint32_t)(kk * 32 + (lane >> 4) * 16);
            uint32_t a[4][4];
            #pragma unroll
            for (int m = 0; m < 4; ++m) {
                uint32_t roff = (uint32_t)((warpRow * 64 + m * 16 + (lane & 15)) * ROWSTRIDE) + kb;
                ldsm_x4(a[m][0], a[m][1], a[m][2], a[m][3], aB + roff);
            }
            uint32_t b[4][2];
            #pragma unroll
            for (int nb = 0; nb < 2; ++nb) {
                uint32_t roff = (uint32_t)((warpCol * 32 + nb * 16 + (lane & 15)) * ROWSTRIDE) + kb;
                uint32_t q0, q1, q2, q3;
                ldsm_x4(q0, q1, q2, q3, bB + roff);
                b[nb * 2 + 0][0] = q0; b[nb * 2 + 0][1] = q2;
                b[nb * 2 + 1][0] = q1; b[nb * 2 + 1][1] = q3;
            }
            #pragma unroll
            for (int m = 0; m < 4; ++m)
                #pragma unroll
                for (int n = 0; n < 4; ++n)
                    mma16816(acc[m][n], a[m][0], a[m][1], a[m][2], a[m][3], b[n][0], b[n][1]);
        }
        __syncthreads();
    }

    // ---- epilogue: two-sided masked min ----
    float rmin[4][2], cmin[4][2];
    #pragma unroll
    for (int x = 0; x < 4; ++x)
        #pragma unroll
        for (int y = 0; y < 2; ++y) { rmin[x][y] = INFINITY; cmin[x][y] = INFINITY; }

    #pragma unroll
    for (int m = 0; m < 4; ++m) {
        #pragma unroll
        for (int h = 0; h < 2; ++h) {
            int rl = warpRow * 64 + m * 16 + h * 8 + (lane >> 2);
            int i  = rowBase + rl;
            float sqi = s_sqrow[rl];
            #pragma unroll
            for (int n = 0; n < 4; ++n) {
                #pragma unroll
                for (int e = 0; e < 2; ++e) {
                    int cl = warpCol * 32 + n * 8 + (lane & 3) * 2 + e;
                    int j  = colBase + cl;
                    float a = acc[m][n][h * 2 + e];
                    if (j != i && j != (i ^ NHALF)) {
                        rmin[m][h] = fminf(rmin[m][h], fmaf(-2.f, a, s_sqcol[cl]));
                        cmin[n][e] = fminf(cmin[n][e], fmaf(-2.f, a, sqi));
                    }
                }
            }
        }
    }

    #pragma unroll
    for (int m = 0; m < 4; ++m)
        #pragma unroll
        for (int h = 0; h < 2; ++h) {
            float v = rmin[m][h];
            v = fminf(v, __shfl_xor_sync(0xFFFFFFFFu, v, 1));
            v = fminf(v, __shfl_xor_sync(0xFFFFFFFFu, v, 2));
            if ((lane & 3) == 0)
                atomicMin(&s_rowmin[warpRow * 64 + m * 16 + h * 8 + (lane >> 2)], f2ord(v));
        }
    if (!diag) {
        #pragma unroll
        for (int n = 0; n < 4; ++n)
            #pragma unroll
            for (int e = 0; e < 2; ++e) {
                float v = cmin[n][e];
                v = fminf(v, __shfl_xor_sync(0xFFFFFFFFu, v, 4));
                v = fminf(v, __shfl_xor_sync(0xFFFFFFFFu, v, 8));
                v = fminf(v, __shfl_xor_sync(0xFFFFFFFFu, v, 16));
                if ((lane >> 2) == 0)
                    atomicMin(&s_colmin[warpCol * 32 + n * 8 + (lane & 3) * 2 + e], f2ord(v));
            }
    }
    __syncthreads();

    if (tid < BM)
        atomicMin(&g_minneg[rowBase + tid], s_rowmin[tid]);
    else if (!diag)
        atomicMin(&g_minneg[colBase + (tid - BM)], s_colmin[tid - BM]);
}

// ---------------- Kernel 3: finalize ----------------
__device__ __forceinline__ float block_reduce_sum(float v, float* sh, int tid) {
    sh[tid] = v;
    __syncthreads();
    for (int s = 512; s; s >>= 1) {
        if (tid < s) sh[tid] += sh[tid + s];
        __syncthreads();
    }
    float r = sh[0];
    __syncthreads();
    return r;
}

__global__ void finalize_kernel(float* __restrict__ out) {
    __shared__ float sh[1024];
    int tid = threadIdx.x;

    float sum_diff = 0.f, sum_rel = 0.f, sum_sq = 0.f;
    float cnt_rel = 0.f, cnt_good = 0.f;

    for (int s = 0; s < B; s += 1024) {
        int i = s + tid;
        float sqi = g_sq[i];
        float d2p = sqi + g_sq[i ^ NHALF] - 2.f * g_posdot[i];
        float hp  = fmaxf(sqrtf(fmaxf(d2p, 1e-14f)), 1e-7f);
        float d2n = sqi + ord2f(g_minneg[i]);
        float hn  = fmaxf(sqrtf(fmaxf(d2n, 1e-14f)), 1e-7f);
        float diff = hp - hn;
        float trip = fmaxf(diff + 0.1f, 0.f);
        sum_diff += diff;
        if (trip > 1e-5f) { sum_rel += trip; cnt_rel += 1.f; }
        if (trip < 1e-5f) cnt_good += 1.f;
        sum_sq += sqi;
    }

    float tot_diff = block_reduce_sum(sum_diff, sh, tid);
    float tot_rel  = block_reduce_sum(sum_rel,  sh, tid);
    float tot_sq   = block_reduce_sum(sum_sq,   sh, tid);
    float tot_crel = block_reduce_sum(cnt_rel,  sh, tid);
    float tot_good = block_reduce_sum(cnt_good, sh, tid);

    if (tid == 0) {
        float nrel = fmaxf(tot_crel, 1.f);
        out[0] = tot_rel / nrel;
        out[1] = tot_diff / (float)B;
        out[2] = tot_good;
        out[3] = (float)B - tot_good;
        out[4] = sqrtf(tot_sq / (float)B);
    }
}

extern "C" void kernel_launch(void* const* d_in, const int* in_sizes, int n_in,
                              void* d_out, int out_size) {
    const float* h1 = (const float*)d_in[0];
    const float* h2 = (const float*)d_in[1];
    (void)in_sizes; (void)n_in; (void)out_size;

    static int smem_set = 0;
    if (!smem_set) {
        cudaFuncSetAttribute(gemm_min_kernel,
                             cudaFuncAttributeMaxDynamicSharedMemorySize, SM_TOTAL);
        smem_set = 1;
    }

    prep_kernel<<<B, 128>>>(h1, h2);
    gemm_min_kernel<<<NB * (NB + 1) / 2, NTHREADS, SM_TOTAL>>>();
    finalize_kernel<<<1, 1024>>>((float*)d_out);
}

// round 6
// speedup vs baseline: 11.2584x; 1.0379x over previous
#include <cuda_runtime.h>
#include <cuda_fp16.h>
#include <math.h>
#include <stdint.h>

#define B       4096
#define D       512
#define NHALF   2048
#define BM      128
#define BN      128
#define KC      64
#define NC      (D / KC)        // 8 chunks
#define NB      (B / BM)        // 32 block-rows
#define NTILES  (NB * (NB + 1) / 2)   // 528
#define NTHREADS 256
#define ROWSTRIDE 144           // 128B data + 16B pad (conflict-free ldmatrix)

#define TILE_BYTES   (BM * ROWSTRIDE)        // 18432
#define STAGE_BYTES  (2 * TILE_BYTES)        // 36864 (A, B)
#define SM_SQROW     (2 * STAGE_BYTES)       // 73728
#define SM_SQCOL     (SM_SQROW + BM * 4)
#define SM_ROWMIN    (SM_SQCOL + BN * 4)
#define SM_COLMIN    (SM_ROWMIN + BM * 4)
#define SM_TOTAL     (SM_COLMIN + BN * 4)    // 75776

// ---- scratch ----
__device__ __half g_h[(size_t)B * D];   // 4 MB
__device__ float g_sq[B];
__device__ float g_posdot[B];
__device__ int   g_minneg[B];
__device__ int   g_done = 0;

__device__ __forceinline__ int f2ord(float f) {
    int i = __float_as_int(f);
    return (i >= 0) ? i : (i ^ 0x7FFFFFFF);
}
__device__ __forceinline__ float ord2f(int i) {
    return __int_as_float((i >= 0) ? i : (i ^ 0x7FFFFFFF));
}

__device__ __forceinline__ void ldsm_x4(uint32_t& r0, uint32_t& r1, uint32_t& r2, uint32_t& r3,
                                        uint32_t addr) {
    asm volatile("ldmatrix.sync.aligned.m8n8.x4.shared.b16 {%0,%1,%2,%3}, [%4];"
                 : "=r"(r0), "=r"(r1), "=r"(r2), "=r"(r3) : "r"(addr));
}

__device__ __forceinline__ void mma16816(float* c, uint32_t a0, uint32_t a1, uint32_t a2,
                                         uint32_t a3, uint32_t b0, uint32_t b1) {
    asm volatile(
        "mma.sync.aligned.m16n8k16.row.col.f32.f16.f16.f32 "
        "{%0,%1,%2,%3}, {%4,%5,%6,%7}, {%8,%9}, {%0,%1,%2,%3};"
        : "+f"(c[0]), "+f"(c[1]), "+f"(c[2]), "+f"(c[3])
        : "r"(a0), "r"(a1), "r"(a2), "r"(a3), "r"(b0), "r"(b1));
}

__device__ __forceinline__ void cp_async16(uint32_t dst, const void* src) {
    asm volatile("cp.async.cg.shared.global [%0], [%1], 16;" :: "r"(dst), "l"(src));
}
#define CP_COMMIT()  asm volatile("cp.async.commit_group;" ::: "memory")
#define CP_WAIT(n)   asm volatile("cp.async.wait_group %0;" :: "n"(n) : "memory")

// ---------------- Kernel 1: prep (pair-fused: block i handles rows i and i+NHALF) ----------------
__global__ void prep_kernel(const float* __restrict__ h1, const float* __restrict__ h2) {
    int i = blockIdx.x;              // 0..NHALF-1
    const float* __restrict__ r1 = h1 + (size_t)i * D;
    const float* __restrict__ r2 = h2 + (size_t)i * D;
    float sqx = 0.f, sqy = 0.f, dot = 0.f;
    for (int k = threadIdx.x; k < D; k += blockDim.x) {
        float x = r1[k];
        float y = r2[k];
        g_h[(size_t)i * D + k]           = __float2half(x);
        g_h[(size_t)(i + NHALF) * D + k] = __float2half(y);
        sqx = fmaf(x, x, sqx);
        sqy = fmaf(y, y, sqy);
        dot = fmaf(x, y, dot);
    }
    #pragma unroll
    for (int o = 16; o; o >>= 1) {
        sqx += __shfl_xor_sync(0xFFFFFFFFu, sqx, o);
        sqy += __shfl_xor_sync(0xFFFFFFFFu, sqy, o);
        dot += __shfl_xor_sync(0xFFFFFFFFu, dot, o);
    }
    __shared__ float sx[4], sy[4], sd[4];
    int w = threadIdx.x >> 5;
    if ((threadIdx.x & 31) == 0) { sx[w] = sqx; sy[w] = sqy; sd[w] = dot; }
    __syncthreads();
    if (threadIdx.x == 0) {
        float X = 0.f, Y = 0.f, T = 0.f;
        #pragma unroll
        for (int j = 0; j < 4; ++j) { X += sx[j]; Y += sy[j]; T += sd[j]; }
        g_sq[i]             = X;
        g_sq[i + NHALF]     = Y;
        g_posdot[i]         = T;
        g_posdot[i + NHALF] = T;
        g_minneg[i]         = 0x7FFFFFFF;
        g_minneg[i + NHALF] = 0x7FFFFFFF;
    }
}

// ---------------- Kernel 2: pipelined fp16 HMMA Gram + two-sided min + fused finalize ----------------
__global__ __launch_bounds__(NTHREADS, 2) void gemm_min_kernel(float* __restrict__ out) {
    extern __shared__ char smem[];
    const uint32_t sb = (uint32_t)__cvta_generic_to_shared(smem);

    const int tid  = threadIdx.x;
    const int wid  = tid >> 5;
    const int lane = tid & 31;
    const int warpRow = wid >> 2;     // 0..1
    const int warpCol = wid & 3;      // 0..3

    // triangular block decode
    int t = blockIdx.x, bi = 0;
    while (t >= NB - bi) { t -= NB - bi; ++bi; }
    const int bj = bi + t;
    const int rowBase = bi * BM;
    const int colBase = bj * BN;
    const bool diag = (bi == bj);

    float* s_sqrow = (float*)(smem + SM_SQROW);
    float* s_sqcol = (float*)(smem + SM_SQCOL);
    int*   s_rowmin = (int*)(smem + SM_ROWMIN);
    int*   s_colmin = (int*)(smem + SM_COLMIN);

    if (tid < BM) {
        s_sqrow[tid]  = g_sq[rowBase + tid];
        s_sqcol[tid]  = g_sq[colBase + tid];
        s_rowmin[tid] = 0x7FFFFFFF;
        s_colmin[tid] = 0x7FFFFFFF;
    }

    // staging: 1024 16B-segs per tile, 2 tiles -> 8 cp.async per thread
    auto stage_load = [&](int s, int kc) {
        const int kel = kc * KC;
        const uint32_t st = sb + (uint32_t)s * STAGE_BYTES;
        #pragma unroll
        for (int l = 0; l < 4; ++l) {
            int sg = tid + l * NTHREADS;
            int r = sg >> 3, c = sg & 7;
            uint32_t o = (uint32_t)(r * ROWSTRIDE + c * 16);
            cp_async16(st + o,              &g_h[(size_t)(rowBase + r) * D + kel + (size_t)c * 8]);
            cp_async16(st + TILE_BYTES + o, &g_h[(size_t)(colBase + r) * D + kel + (size_t)c * 8]);
        }
    };

    float acc[4][4][4];
    #pragma unroll
    for (int m = 0; m < 4; ++m)
        #pragma unroll
        for (int n = 0; n < 4; ++n)
            #pragma unroll
            for (int c = 0; c < 4; ++c) acc[m][n][c] = 0.f;

    stage_load(0, 0);
    CP_COMMIT();

    for (int kc = 0; kc < NC; ++kc) {
        if (kc + 1 < NC) {
            stage_load((kc + 1) & 1, kc + 1);
            CP_COMMIT();
            CP_WAIT(1);
        } else {
            CP_WAIT(0);
        }
        __syncthreads();

        const uint32_t aB = sb + (uint32_t)(kc & 1) * STAGE_BYTES;
        const uint32_t bB = aB + TILE_BYTES;

        #pragma unroll
        for (int kk = 0; kk < 4; ++kk) {
            const uint32_t kb = (uint32_t)(kk * 32 + (lane >> 4) * 16);
            uint32_t a[4][4];
            #pragma unroll
            for (int m = 0; m < 4; ++m) {
                uint32_t roff = (uint32_t)((warpRow * 64 + m * 16 + (lane & 15)) * ROWSTRIDE) + kb;
                ldsm_x4(a[m][0], a[m][1], a[m][2], a[m][3], aB + roff);
            }
            uint32_t b[4][2];
            #pragma unroll
            for (int nb = 0; nb < 2; ++nb) {
                uint32_t roff = (uint32_t)((warpCol * 32 + nb * 16 + (lane & 15)) * ROWSTRIDE) + kb;
                uint32_t q0, q1, q2, q3;
                ldsm_x4(q0, q1, q2, q3, bB + roff);
                b[nb * 2 + 0][0] = q0; b[nb * 2 + 0][1] = q2;
                b[nb * 2 + 1][0] = q1; b[nb * 2 + 1][1] = q3;
            }
            #pragma unroll
            for (int m = 0; m < 4; ++m)
                #pragma unroll
                for (int n = 0; n < 4; ++n)
                    mma16816(acc[m][n], a[m][0], a[m][1], a[m][2], a[m][3], b[n][0], b[n][1]);
        }
        __syncthreads();
    }

    // ---- epilogue: two-sided masked min ----
    float rmin[4][2], cmin[4][2];
    #pragma unroll
    for (int x = 0; x < 4; ++x)
        #pragma unroll
        for (int y = 0; y < 2; ++y) { rmin[x][y] = INFINITY; cmin[x][y] = INFINITY; }

    #pragma unroll
    for (int m = 0; m < 4; ++m) {
        #pragma unroll
        for (int h = 0; h < 2; ++h) {
            int rl = warpRow * 64 + m * 16 + h * 8 + (lane >> 2);
            int i  = rowBase + rl;
            float sqi = s_sqrow[rl];
            #pragma unroll
            for (int n = 0; n < 4; ++n) {
                #pragma unroll
                for (int e = 0; e < 2; ++e) {
                    int cl = warpCol * 32 + n * 8 + (lane & 3) * 2 + e;
                    int j  = colBase + cl;
                    float a = acc[m][n][h * 2 + e];
                    if (j != i && j != (i ^ NHALF)) {
                        rmin[m][h] = fminf(rmin[m][h], fmaf(-2.f, a, s_sqcol[cl]));
                        cmin[n][e] = fminf(cmin[n][e], fmaf(-2.f, a, sqi));
                    }
                }
            }
        }
    }

    #pragma unroll
    for (int m = 0; m < 4; ++m)
        #pragma unroll
        for (int h = 0; h < 2; ++h) {
            float v = rmin[m][h];
            v = fminf(v, __shfl_xor_sync(0xFFFFFFFFu, v, 1));
            v = fminf(v, __shfl_xor_sync(0xFFFFFFFFu, v, 2));
            if ((lane & 3) == 0)
                atomicMin(&s_rowmin[warpRow * 64 + m * 16 + h * 8 + (lane >> 2)], f2ord(v));
        }
    if (!diag) {
        #pragma unroll
        for (int n = 0; n < 4; ++n)
            #pragma unroll
            for (int e = 0; e < 2; ++e) {
                float v = cmin[n][e];
                v = fminf(v, __shfl_xor_sync(0xFFFFFFFFu, v, 4));
                v = fminf(v, __shfl_xor_sync(0xFFFFFFFFu, v, 8));
                v = fminf(v, __shfl_xor_sync(0xFFFFFFFFu, v, 16));
                if ((lane >> 2) == 0)
                    atomicMin(&s_colmin[warpCol * 32 + n * 8 + (lane & 3) * 2 + e], f2ord(v));
            }
    }
    __syncthreads();

    if (tid < BM)
        atomicMin(&g_minneg[rowBase + tid], s_rowmin[tid]);
    else if (!diag)
        atomicMin(&g_minneg[colBase + (tid - BM)], s_colmin[tid - BM]);

    // ---- fused finalize: last CTA to finish does the scalar reduction ----
    __threadfence();
    __shared__ int s_last;
    if (tid == 0) s_last = (atomicAdd(&g_done, 1) == NTILES - 1) ? 1 : 0;
    __syncthreads();
    if (!s_last) return;
    if (tid == 0) g_done = 0;   // reset for next graph replay
    __threadfence();

    float sum_diff = 0.f, sum_rel = 0.f, sum_sq = 0.f, cnt_rel = 0.f, cnt_good = 0.f;
    for (int i = tid; i < B; i += NTHREADS) {
        float sqi = g_sq[i];
        float d2p = sqi + g_sq[i ^ NHALF] - 2.f * g_posdot[i];
        float hp  = fmaxf(sqrtf(fmaxf(d2p, 1e-14f)), 1e-7f);
        float d2n = sqi + ord2f(g_minneg[i]);
        float hn  = fmaxf(sqrtf(fmaxf(d2n, 1e-14f)), 1e-7f);
        float diff = hp - hn;
        float trip = fmaxf(diff + 0.1f, 0.f);
        sum_diff += diff;
        if (trip > 1e-5f) { sum_rel += trip; cnt_rel += 1.f; }
        if (trip < 1e-5f) cnt_good += 1.f;
        sum_sq += sqi;
    }
    #pragma unroll
    for (int o = 16; o; o >>= 1) {
        sum_diff += __shfl_xor_sync(0xFFFFFFFFu, sum_diff, o);
        sum_rel  += __shfl_xor_sync(0xFFFFFFFFu, sum_rel,  o);
        sum_sq   += __shfl_xor_sync(0xFFFFFFFFu, sum_sq,   o);
        cnt_rel  += __shfl_xor_sync(0xFFFFFFFFu, cnt_rel,  o);
        cnt_good += __shfl_xor_sync(0xFFFFFFFFu, cnt_good, o);
    }
    float* red = (float*)smem;   // reuse stage smem (post-GEMM)
    if (lane == 0) {
        red[wid * 5 + 0] = sum_diff;
        red[wid * 5 + 1] = sum_rel;
        red[wid * 5 + 2] = sum_sq;
        red[wid * 5 + 3] = cnt_rel;
        red[wid * 5 + 4] = cnt_good;
    }
    __syncthreads();
    if (tid == 0) {
        float td = 0.f, tr = 0.f, ts = 0.f, tc = 0.f, tg = 0.f;
        #pragma unroll
        for (int w = 0; w < NTHREADS / 32; ++w) {
            td += red[w * 5 + 0];
            tr += red[w * 5 + 1];
            ts += red[w * 5 + 2];
            tc += red[w * 5 + 3];
            tg += red[w * 5 + 4];
        }
        out[0] = tr / fmaxf(tc, 1.f);
        out[1] = td / (float)B;
        out[2] = tg;
        out[3] = (float)B - tg;
        out[4] = sqrtf(ts / (float)B);
    }
}

extern "C" void kernel_launch(void* const* d_in, const int* in_sizes, int n_in,
                              void* d_out, int out_size) {
    const float* h1 = (const float*)d_in[0];
    const float* h2 = (const float*)d_in[1];
    (void)in_sizes; (void)n_in; (void)out_size;

    static int smem_set = 0;
    if (!smem_set) {
        cudaFuncSetAttribute(gemm_min_kernel,
                             cudaFuncAttributeMaxDynamicSharedMemorySize, SM_TOTAL);
        smem_set = 1;
    }

    prep_kernel<<<NHALF, 128>>>(h1, h2);
    gemm_min_kernel<<<NTILES, NTHREADS, SM_TOTAL>>>((float*)d_out);
}